// round 6
// baseline (speedup 1.0000x reference)
#include <cuda_runtime.h>
#include <cuda_fp16.h>
#include <math.h>
#include <stdint.h>

#define DIM     1024
#define HIDDEN  1024
#define NE      8
#define T_TOK   32768
#define KT      64          // k-tile in halfs (128B of fp16)
#define NKT     16          // 1024 / 64
#define SH      72          // padded smem row, halfs (144B: conflict-free for ldmatrix)
#define SHB     144

// ---------------- device scratch ----------------
__device__ int    g_count[NE];
__device__ int    g_offset[NE];
__device__ int    g_tok[NE * T_TOK];
__device__ float  g_wt[NE * T_TOK];
__device__ int    g_eA[T_TOK], g_pA[T_TOK], g_eB[T_TOK], g_pB[T_TOK];
__device__ __align__(16) __half g_x16[(size_t)T_TOK * DIM];
__device__ __align__(16) __half g_wg16[(size_t)NE * HIDDEN * DIM];
__device__ __align__(16) __half g_wu16[(size_t)NE * HIDDEN * DIM];
__device__ __align__(16) __half g_wd16[(size_t)NE * DIM * HIDDEN];
__device__ __align__(16) __half g_h[(size_t)2 * T_TOK * HIDDEN];
__device__ __align__(16) float  g_y[(size_t)2 * T_TOK * DIM];

// ---------------- helpers ----------------
__device__ __forceinline__ uint32_t sptr(const void* p) {
    return (uint32_t)__cvta_generic_to_shared(p);
}
__device__ __forceinline__ void cp16(uint32_t dst, const void* src) {
    asm volatile("cp.async.cg.shared.global [%0], [%1], 16;" :: "r"(dst), "l"(src));
}
__device__ __forceinline__ void cp_commit() {
    asm volatile("cp.async.commit_group;" ::: "memory");
}
template<int N> __device__ __forceinline__ void cp_wait() {
    asm volatile("cp.async.wait_group %0;" :: "n"(N) : "memory");
}
__device__ __forceinline__ void ldsm4(uint32_t* r, uint32_t a) {
    asm volatile("ldmatrix.sync.aligned.m8n8.x4.shared.b16 {%0,%1,%2,%3}, [%4];"
                 : "=r"(r[0]), "=r"(r[1]), "=r"(r[2]), "=r"(r[3]) : "r"(a));
}
__device__ __forceinline__ void mma16(float* c, const uint32_t* a, uint32_t b0, uint32_t b1) {
    asm volatile("mma.sync.aligned.m16n8k16.row.col.f32.f16.f16.f32 "
                 "{%0,%1,%2,%3},{%4,%5,%6,%7},{%8,%9},{%0,%1,%2,%3};"
                 : "+f"(c[0]), "+f"(c[1]), "+f"(c[2]), "+f"(c[3])
                 : "r"(a[0]), "r"(a[1]), "r"(a[2]), "r"(a[3]), "r"(b0), "r"(b1));
}
__device__ __forceinline__ float silu(float g) {
    return g * (1.f / (1.f + __expf(-g)));
}

// ---------------- fp32 -> fp16 conversion (dest selected in device code) ----------------
__global__ __launch_bounds__(256) void k_conv(const float* __restrict__ s, int which, int n4) {
    __half* d = (which == 0) ? g_x16 : (which == 1) ? g_wg16 : (which == 2) ? g_wu16 : g_wd16;
    int i = blockIdx.x * 256 + threadIdx.x;
    if (i < n4) {
        float4 v = ((const float4*)s)[i];
        __half2* o = (__half2*)d + (size_t)i * 2;
        o[0] = __floats2half2_rn(v.x, v.y);
        o[1] = __floats2half2_rn(v.z, v.w);
    }
}

// ---------------- init / router ----------------
__global__ void k_zero_counts() { if (threadIdx.x < NE) g_count[threadIdx.x] = 0; }
__global__ void k_offsets() {
    if (threadIdx.x == 0) {
        int s = 0;
        #pragma unroll
        for (int e = 0; e < NE; e++) { g_offset[e] = s; s += g_count[e]; }
    }
}

__global__ __launch_bounds__(256) void k_router(const float* __restrict__ x,
                                                const float* __restrict__ gate_w) {
    int warp = blockIdx.x * 8 + (threadIdx.x >> 5);
    int lane = threadIdx.x & 31;
    if (warp >= T_TOK) return;
    const float* xr = x + (size_t)warp * DIM;
    float acc[NE];
    #pragma unroll
    for (int e = 0; e < NE; e++) acc[e] = 0.f;
    #pragma unroll
    for (int j = 0; j < DIM / 128; j++) {
        int d = j * 128 + lane * 4;
        float4 xv = *(const float4*)(xr + d);
        #pragma unroll
        for (int e = 0; e < NE; e++) {
            float4 gv = *(const float4*)(gate_w + e * DIM + d);
            acc[e] += xv.x * gv.x + xv.y * gv.y + xv.z * gv.z + xv.w * gv.w;
        }
    }
    #pragma unroll
    for (int off = 16; off > 0; off >>= 1)
        #pragma unroll
        for (int e = 0; e < NE; e++)
            acc[e] += __shfl_xor_sync(0xffffffffu, acc[e], off);
    if (lane == 0) {
        int i0 = 0;
        #pragma unroll
        for (int e = 1; e < NE; e++) if (acc[e] > acc[i0]) i0 = e;
        int i1 = -1;
        #pragma unroll
        for (int e = 0; e < NE; e++) {
            if (e == i0) continue;
            if (i1 < 0 || acc[e] > acc[i1]) i1 = e;
        }
        float s0 = 1.f / (1.f + expf(-acc[i0]));
        float s1 = 1.f / (1.f + expf(-acc[i1]));
        float inv = 1.f / (s0 + s1 + 1e-9f);
        int p0 = atomicAdd(&g_count[i0], 1);
        g_tok[i0 * T_TOK + p0] = warp; g_wt[i0 * T_TOK + p0] = s0 * inv;
        int p1 = atomicAdd(&g_count[i1], 1);
        g_tok[i1 * T_TOK + p1] = warp; g_wt[i1 * T_TOK + p1] = s1 * inv;
        g_eA[warp] = i0; g_pA[warp] = p0;
        g_eB[warp] = i1; g_pB[warp] = p1;
    }
}

// ---------------- GEMM1 (fp16 mma): h = silu(Xg Wg^T) * (Xg Wu^T) ----------------
// Block 256(M) x 64(N) dual-B, 512 threads (16 warps: 8 along M x 2 along N).
// smem/stage: A 256 rows + Bg 64 + Bu 64 = 384 rows x 144B = 55296 B; x2 stages.
#define G1_BUF  (384 * SHB)
#define G1_SMEM (2 * G1_BUF)
__global__ __launch_bounds__(512, 1) void k_gemm1() {
    extern __shared__ char smem[];
    int e   = blockIdx.z;
    int cnt = g_count[e];
    int m0  = blockIdx.y * 256;
    if (m0 >= cnt) return;
    int n0  = blockIdx.x * 64;
    int tid = threadIdx.x, lane = tid & 31, wid = tid >> 5;
    int wm  = wid & 7, wn = wid >> 3;

    const __half* Wg = g_wg16 + (size_t)e * HIDDEN * DIM;
    const __half* Wu = g_wu16 + (size_t)e * HIDDEN * DIM;

    // A: 256 rows x 8 chunks = 2048 slots / 512 thr = 4 each
    const __half* arow[4];
    #pragma unroll
    for (int it = 0; it < 4; it++) {
        int flat = tid + it * 512;
        int m    = flat >> 3;
        int gm   = m0 + m;
        int tok  = g_tok[e * T_TOK + (gm < cnt ? gm : 0)];
        arow[it] = g_x16 + (size_t)tok * DIM + (flat & 7) * 8;
    }
    // Bg/Bu: 64 rows x 8 chunks = 512 slots each -> 1 per thread
    const __half* grow = Wg + (size_t)(n0 + (tid >> 3)) * DIM + (tid & 7) * 8;
    const __half* urow = Wu + (size_t)(n0 + (tid >> 3)) * DIM + (tid & 7) * 8;

    uint32_t sbase = sptr(smem);
    uint32_t dA[4];
    #pragma unroll
    for (int it = 0; it < 4; it++) {
        int flat = tid + it * 512;
        dA[it] = sbase + (uint32_t)((flat >> 3) * SHB + (flat & 7) * 16);
    }
    uint32_t dG = sbase + (uint32_t)(256 * SHB + (tid >> 3) * SHB + (tid & 7) * 16);
    uint32_t dU = sbase + (uint32_t)(320 * SHB + (tid >> 3) * SHB + (tid & 7) * 16);

    float accg[2][4][4], accu[2][4][4];
    #pragma unroll
    for (int mt = 0; mt < 2; mt++)
        #pragma unroll
        for (int nt = 0; nt < 4; nt++)
            #pragma unroll
            for (int i = 0; i < 4; i++) { accg[mt][nt][i] = 0.f; accu[mt][nt][i] = 0.f; }

    uint32_t aOff = (uint32_t)((wm * 32 + (lane & 15)) * SHB + ((lane >> 4) & 1) * 16);
    uint32_t bRow = (uint32_t)(wn * 32 + (lane & 7) + ((lane >> 4) & 1) * 8);
    uint32_t gOff = 256 * SHB + bRow * SHB + ((lane >> 3) & 1) * 16;
    uint32_t uOff = 320 * SHB + bRow * SHB + ((lane >> 3) & 1) * 16;

    #pragma unroll
    for (int it = 0; it < 4; it++) cp16(dA[it], arow[it]);
    cp16(dG, grow); cp16(dU, urow);
    cp_commit();

    for (int kt = 0; kt < NKT; kt++) {
        uint32_t cur = (kt & 1) * G1_BUF;
        if (kt + 1 < NKT) {
            uint32_t nb = ((kt + 1) & 1) * G1_BUF;
            int ko = (kt + 1) * KT;
            #pragma unroll
            for (int it = 0; it < 4; it++) cp16(dA[it] + nb, arow[it] + ko);
            cp16(dG + nb, grow + ko); cp16(dU + nb, urow + ko);
            cp_commit();
            cp_wait<1>();
        } else {
            cp_wait<0>();
        }
        __syncthreads();

        uint32_t aB = sbase + cur + aOff;
        uint32_t gB = sbase + cur + gOff;
        uint32_t uB = sbase + cur + uOff;
        #pragma unroll
        for (int ks = 0; ks < 4; ks++) {
            uint32_t a[2][4], bg[2][4], bu[2][4];
            ldsm4(a[0], aB + ks * 32);
            ldsm4(a[1], aB + 16 * SHB + ks * 32);
            ldsm4(bg[0], gB + ks * 32);
            ldsm4(bg[1], gB + 16 * SHB + ks * 32);
            ldsm4(bu[0], uB + ks * 32);
            ldsm4(bu[1], uB + 16 * SHB + ks * 32);
            #pragma unroll
            for (int mt = 0; mt < 2; mt++)
                #pragma unroll
                for (int nt = 0; nt < 4; nt++) {
                    int g = nt >> 1, h = (nt & 1) * 2;
                    mma16(accg[mt][nt], a[mt], bg[g][h], bg[g][h + 1]);
                    mma16(accu[mt][nt], a[mt], bu[g][h], bu[g][h + 1]);
                }
        }
        __syncthreads();
    }

    int base = g_offset[e];
    #pragma unroll
    for (int mt = 0; mt < 2; mt++) {
        #pragma unroll
        for (int half = 0; half < 2; half++) {
            int gm = m0 + wm * 32 + mt * 16 + (lane >> 2) + half * 8;
            if (gm < cnt) {
                __half* hp = &g_h[(size_t)(base + gm) * HIDDEN + n0 + wn * 32 + (lane & 3) * 2];
                #pragma unroll
                for (int nt = 0; nt < 4; nt++) {
                    float gx = accg[mt][nt][half * 2 + 0], ux = accu[mt][nt][half * 2 + 0];
                    float gy = accg[mt][nt][half * 2 + 1], uy = accu[mt][nt][half * 2 + 1];
                    *(__half2*)(hp + nt * 8) = __floats2half2_rn(silu(gx) * ux, silu(gy) * uy);
                }
            }
        }
    }
}

// ---------------- GEMM2 (fp16 mma): y = (h Wd^T) * wt ----------------
// Block 256(M) x 128(N), 512 threads (16 warps: 4 along M x 4 along N), warp tile 64x32.
#define G2_BUF  (384 * SHB)
#define G2_SMEM (2 * G2_BUF)
__global__ __launch_bounds__(512, 1) void k_gemm2() {
    extern __shared__ char smem[];
    int e   = blockIdx.z;
    int cnt = g_count[e];
    int m0  = blockIdx.y * 256;
    if (m0 >= cnt) return;
    int n0  = blockIdx.x * 128;
    int tid = threadIdx.x, lane = tid & 31, wid = tid >> 5;
    int wm  = wid & 3, wn = wid >> 2;

    const __half* Wd = g_wd16 + (size_t)e * DIM * HIDDEN;
    int base = g_offset[e];

    // A: 256 rows x 8 chunks = 2048 / 512 = 4 each; B: 128 rows x 8 = 1024 / 512 = 2 each
    const __half* arow[4];
    #pragma unroll
    for (int it = 0; it < 4; it++) {
        int flat = tid + it * 512;
        int m    = flat >> 3;
        int gm   = m0 + m;
        arow[it] = g_h + (size_t)(base + (gm < cnt ? gm : 0)) * HIDDEN + (flat & 7) * 8;
    }
    const __half* brow[2];
    #pragma unroll
    for (int it = 0; it < 2; it++) {
        int flat = tid + it * 512;
        brow[it] = Wd + (size_t)(n0 + (flat >> 3)) * HIDDEN + (flat & 7) * 8;
    }
    uint32_t sbase = sptr(smem);
    uint32_t dA[4], dB[2];
    #pragma unroll
    for (int it = 0; it < 4; it++) {
        int flat = tid + it * 512;
        dA[it] = sbase + (uint32_t)((flat >> 3) * SHB + (flat & 7) * 16);
    }
    #pragma unroll
    for (int it = 0; it < 2; it++) {
        int flat = tid + it * 512;
        dB[it] = sbase + (uint32_t)(256 * SHB + (flat >> 3) * SHB + (flat & 7) * 16);
    }

    float acc[4][4][4];
    #pragma unroll
    for (int mt = 0; mt < 4; mt++)
        #pragma unroll
        for (int nt = 0; nt < 4; nt++)
            #pragma unroll
            for (int i = 0; i < 4; i++) acc[mt][nt][i] = 0.f;

    uint32_t aOff = (uint32_t)((wm * 64 + (lane & 15)) * SHB + ((lane >> 4) & 1) * 16);
    uint32_t bOff = 256 * SHB +
                    (uint32_t)((wn * 32 + (lane & 7) + ((lane >> 4) & 1) * 8) * SHB +
                               ((lane >> 3) & 1) * 16);

    #pragma unroll
    for (int it = 0; it < 4; it++) cp16(dA[it], arow[it]);
    #pragma unroll
    for (int it = 0; it < 2; it++) cp16(dB[it], brow[it]);
    cp_commit();

    for (int kt = 0; kt < NKT; kt++) {
        uint32_t cur = (kt & 1) * G2_BUF;
        if (kt + 1 < NKT) {
            uint32_t nb = ((kt + 1) & 1) * G2_BUF;
            int ko = (kt + 1) * KT;
            #pragma unroll
            for (int it = 0; it < 4; it++) cp16(dA[it] + nb, arow[it] + ko);
            #pragma unroll
            for (int it = 0; it < 2; it++) cp16(dB[it] + nb, brow[it] + ko);
            cp_commit();
            cp_wait<1>();
        } else {
            cp_wait<0>();
        }
        __syncthreads();

        uint32_t aB = sbase + cur + aOff;
        uint32_t bB = sbase + cur + bOff;
        #pragma unroll
        for (int ks = 0; ks < 4; ks++) {
            uint32_t a[4][4], b[2][4];
            #pragma unroll
            for (int mt = 0; mt < 4; mt++)
                ldsm4(a[mt], aB + mt * 16 * SHB + ks * 32);
            ldsm4(b[0], bB + ks * 32);
            ldsm4(b[1], bB + 16 * SHB + ks * 32);
            #pragma unroll
            for (int mt = 0; mt < 4; mt++)
                #pragma unroll
                for (int nt = 0; nt < 4; nt++) {
                    int g = nt >> 1, h = (nt & 1) * 2;
                    mma16(acc[mt][nt], a[mt], b[g][h], b[g][h + 1]);
                }
        }
        __syncthreads();
    }

    #pragma unroll
    for (int mt = 0; mt < 4; mt++) {
        #pragma unroll
        for (int half = 0; half < 2; half++) {
            int gm = m0 + wm * 64 + mt * 16 + (lane >> 2) + half * 8;
            if (gm < cnt) {
                float w = g_wt[e * T_TOK + gm];
                float* yp = &g_y[(size_t)(base + gm) * DIM + n0 + wn * 32 + (lane & 3) * 2];
                #pragma unroll
                for (int nt = 0; nt < 4; nt++) {
                    float2 o;
                    o.x = acc[mt][nt][half * 2 + 0] * w;
                    o.y = acc[mt][nt][half * 2 + 1] * w;
                    *(float2*)(yp + nt * 8) = o;
                }
            }
        }
    }
}

// ---------------- combine ----------------
__global__ __launch_bounds__(256) void k_combine(float* __restrict__ out) {
    int t = blockIdx.x;
    int c = threadIdx.x * 4;
    int sA = g_offset[g_eA[t]] + g_pA[t];
    int sB = g_offset[g_eB[t]] + g_pB[t];
    float4 a = *(const float4*)&g_y[(size_t)sA * DIM + c];
    float4 b = *(const float4*)&g_y[(size_t)sB * DIM + c];
    *(float4*)&out[(size_t)t * DIM + c] = make_float4(a.x + b.x, a.y + b.y, a.z + b.z, a.w + b.w);
}

// ---------------- launch ----------------
extern "C" void kernel_launch(void* const* d_in, const int* in_sizes, int n_in,
                              void* d_out, int out_size) {
    const float* x         = (const float*)d_in[0];
    const float* gate_w    = (const float*)d_in[1];
    const float* gate_proj = (const float*)d_in[2];
    const float* up_proj   = (const float*)d_in[3];
    const float* down_proj = (const float*)d_in[4];
    float* out = (float*)d_out;

    cudaFuncSetAttribute(k_gemm1, cudaFuncAttributeMaxDynamicSharedMemorySize, G1_SMEM);
    cudaFuncSetAttribute(k_gemm2, cudaFuncAttributeMaxDynamicSharedMemorySize, G2_SMEM);

    int n4x = T_TOK * DIM / 4;
    int n4w = NE * HIDDEN * DIM / 4;
    k_conv<<<(n4x + 255) / 256, 256>>>(x, 0, n4x);
    k_conv<<<(n4w + 255) / 256, 256>>>(gate_proj, 1, n4w);
    k_conv<<<(n4w + 255) / 256, 256>>>(up_proj, 2, n4w);
    k_conv<<<(n4w + 255) / 256, 256>>>(down_proj, 3, n4w);

    k_zero_counts<<<1, 32>>>();
    k_router<<<T_TOK / 8, 256>>>(x, gate_w);
    k_offsets<<<1, 32>>>();
    k_gemm1<<<dim3(HIDDEN / 64, T_TOK / 256, NE), 512, G1_SMEM>>>();
    k_gemm2<<<dim3(DIM / 128, T_TOK / 256, NE), 512, G2_SMEM>>>();
    k_combine<<<T_TOK, 256>>>(out);
}

// round 7
// speedup vs baseline: 1.1190x; 1.1190x over previous
#include <cuda_runtime.h>
#include <cuda_fp16.h>
#include <math.h>
#include <stdint.h>

#define DIM     1024
#define HIDDEN  1024
#define NE      8
#define T_TOK   32768
#define KT      64          // k-tile in halfs (128B of fp16)
#define NKT     16          // 1024 / 64
#define SH      72          // padded smem row, halfs (144B: conflict-free for ldmatrix)
#define SHB     144

// ---------------- device scratch ----------------
__device__ int    g_count[NE];
__device__ int    g_offset[NE];
__device__ int    g_tok[NE * T_TOK];
__device__ float  g_wt[NE * T_TOK];
__device__ int    g_eA[T_TOK], g_pA[T_TOK], g_eB[T_TOK], g_pB[T_TOK];
__device__ __align__(16) __half g_x16[(size_t)T_TOK * DIM];
__device__ __align__(16) __half g_wg16[(size_t)NE * HIDDEN * DIM];
__device__ __align__(16) __half g_wu16[(size_t)NE * HIDDEN * DIM];
__device__ __align__(16) __half g_wd16[(size_t)NE * DIM * HIDDEN];
__device__ __align__(16) __half g_h[(size_t)2 * T_TOK * HIDDEN];
__device__ __align__(16) float  g_y[(size_t)2 * T_TOK * DIM];

// ---------------- helpers ----------------
__device__ __forceinline__ uint32_t sptr(const void* p) {
    return (uint32_t)__cvta_generic_to_shared(p);
}
__device__ __forceinline__ void cp16(uint32_t dst, const void* src) {
    asm volatile("cp.async.cg.shared.global [%0], [%1], 16;" :: "r"(dst), "l"(src));
}
__device__ __forceinline__ void cp_commit() {
    asm volatile("cp.async.commit_group;" ::: "memory");
}
template<int N> __device__ __forceinline__ void cp_wait() {
    asm volatile("cp.async.wait_group %0;" :: "n"(N) : "memory");
}
__device__ __forceinline__ void ldsm4(uint32_t* r, uint32_t a) {
    asm volatile("ldmatrix.sync.aligned.m8n8.x4.shared.b16 {%0,%1,%2,%3}, [%4];"
                 : "=r"(r[0]), "=r"(r[1]), "=r"(r[2]), "=r"(r[3]) : "r"(a));
}
__device__ __forceinline__ void mma16(float* c, const uint32_t* a, uint32_t b0, uint32_t b1) {
    asm volatile("mma.sync.aligned.m16n8k16.row.col.f32.f16.f16.f32 "
                 "{%0,%1,%2,%3},{%4,%5,%6,%7},{%8,%9},{%0,%1,%2,%3};"
                 : "+f"(c[0]), "+f"(c[1]), "+f"(c[2]), "+f"(c[3])
                 : "r"(a[0]), "r"(a[1]), "r"(a[2]), "r"(a[3]), "r"(b0), "r"(b1));
}
__device__ __forceinline__ float silu(float g) {
    return g * (1.f / (1.f + __expf(-g)));
}

// ---------------- fp32 -> fp16 conversions ----------------
__global__ __launch_bounds__(256) void k_convx(const float* __restrict__ s, int n4) {
    int i = blockIdx.x * 256 + threadIdx.x;
    if (i < n4) {
        float4 v = ((const float4*)s)[i];
        __half2* o = (__half2*)g_x16 + (size_t)i * 2;
        o[0] = __floats2half2_rn(v.x, v.y);
        o[1] = __floats2half2_rn(v.z, v.w);
    }
}
__global__ __launch_bounds__(256) void k_convw(const float* __restrict__ wg,
                                               const float* __restrict__ wu,
                                               const float* __restrict__ wd, int n4) {
    int which = blockIdx.y;
    const float* s = (which == 0) ? wg : (which == 1) ? wu : wd;
    __half* d = (which == 0) ? g_wg16 : (which == 1) ? g_wu16 : g_wd16;
    int i = blockIdx.x * 256 + threadIdx.x;
    if (i < n4) {
        float4 v = ((const float4*)s)[i];
        __half2* o = (__half2*)d + (size_t)i * 2;
        o[0] = __floats2half2_rn(v.x, v.y);
        o[1] = __floats2half2_rn(v.z, v.w);
    }
}

// ---------------- init / router ----------------
__global__ void k_zero_counts() { if (threadIdx.x < NE) g_count[threadIdx.x] = 0; }
__global__ void k_offsets() {
    if (threadIdx.x == 0) {
        int s = 0;
        #pragma unroll
        for (int e = 0; e < NE; e++) { g_offset[e] = s; s += g_count[e]; }
    }
}

__global__ __launch_bounds__(256) void k_router(const float* __restrict__ x,
                                                const float* __restrict__ gate_w) {
    int warp = blockIdx.x * 8 + (threadIdx.x >> 5);
    int lane = threadIdx.x & 31;
    if (warp >= T_TOK) return;
    const float* xr = x + (size_t)warp * DIM;
    float acc[NE];
    #pragma unroll
    for (int e = 0; e < NE; e++) acc[e] = 0.f;
    #pragma unroll
    for (int j = 0; j < DIM / 128; j++) {
        int d = j * 128 + lane * 4;
        float4 xv = *(const float4*)(xr + d);
        #pragma unroll
        for (int e = 0; e < NE; e++) {
            float4 gv = *(const float4*)(gate_w + e * DIM + d);
            acc[e] += xv.x * gv.x + xv.y * gv.y + xv.z * gv.z + xv.w * gv.w;
        }
    }
    #pragma unroll
    for (int off = 16; off > 0; off >>= 1)
        #pragma unroll
        for (int e = 0; e < NE; e++)
            acc[e] += __shfl_xor_sync(0xffffffffu, acc[e], off);
    if (lane == 0) {
        int i0 = 0;
        #pragma unroll
        for (int e = 1; e < NE; e++) if (acc[e] > acc[i0]) i0 = e;
        int i1 = -1;
        #pragma unroll
        for (int e = 0; e < NE; e++) {
            if (e == i0) continue;
            if (i1 < 0 || acc[e] > acc[i1]) i1 = e;
        }
        float s0 = 1.f / (1.f + expf(-acc[i0]));
        float s1 = 1.f / (1.f + expf(-acc[i1]));
        float inv = 1.f / (s0 + s1 + 1e-9f);
        int p0 = atomicAdd(&g_count[i0], 1);
        g_tok[i0 * T_TOK + p0] = warp; g_wt[i0 * T_TOK + p0] = s0 * inv;
        int p1 = atomicAdd(&g_count[i1], 1);
        g_tok[i1 * T_TOK + p1] = warp; g_wt[i1 * T_TOK + p1] = s1 * inv;
        g_eA[warp] = i0; g_pA[warp] = p0;
        g_eB[warp] = i1; g_pB[warp] = p1;
    }
}

// ---------------- GEMM1 (fp16 mma): h = silu(Xg Wg^T) * (Xg Wu^T) ----------------
// Block 128(M) x 64(N) dual-B, 256 thr, 3-stage cp.async pipeline.
#define G1_BUF  (256 * SHB)
#define G1_SMEM (3 * G1_BUF)
__global__ __launch_bounds__(256, 2) void k_gemm1() {
    extern __shared__ char smem[];
    int e   = blockIdx.z;
    int cnt = g_count[e];
    int m0  = blockIdx.y * 128;
    if (m0 >= cnt) return;
    int n0  = blockIdx.x * 64;
    int tid = threadIdx.x, lane = tid & 31, wid = tid >> 5;
    int wm  = wid & 3, wn = wid >> 2;

    const __half* Wg = g_wg16 + (size_t)e * HIDDEN * DIM;
    const __half* Wu = g_wu16 + (size_t)e * HIDDEN * DIM;

    const __half* arow[4];
    #pragma unroll
    for (int it = 0; it < 4; it++) {
        int flat = tid + it * 256;
        int m    = flat >> 3;
        int gm   = m0 + m;
        int tok  = g_tok[e * T_TOK + (gm < cnt ? gm : 0)];
        arow[it] = g_x16 + (size_t)tok * DIM + (flat & 7) * 8;
    }
    const __half* grow[2];
    const __half* urow[2];
    #pragma unroll
    for (int it = 0; it < 2; it++) {
        int flat = tid + it * 256;
        int n    = flat >> 3;
        grow[it] = Wg + (size_t)(n0 + n) * DIM + (flat & 7) * 8;
        urow[it] = Wu + (size_t)(n0 + n) * DIM + (flat & 7) * 8;
    }
    uint32_t sbase = sptr(smem);
    uint32_t dA[4], dG[2], dU[2];
    #pragma unroll
    for (int it = 0; it < 4; it++) {
        int flat = tid + it * 256;
        dA[it] = sbase + (uint32_t)((flat >> 3) * SHB + (flat & 7) * 16);
    }
    #pragma unroll
    for (int it = 0; it < 2; it++) {
        int flat = tid + it * 256;
        dG[it] = sbase + (uint32_t)(128 * SHB + (flat >> 3) * SHB + (flat & 7) * 16);
        dU[it] = sbase + (uint32_t)(192 * SHB + (flat >> 3) * SHB + (flat & 7) * 16);
    }

    float accg[2][4][4], accu[2][4][4];
    #pragma unroll
    for (int mt = 0; mt < 2; mt++)
        #pragma unroll
        for (int nt = 0; nt < 4; nt++)
            #pragma unroll
            for (int i = 0; i < 4; i++) { accg[mt][nt][i] = 0.f; accu[mt][nt][i] = 0.f; }

    uint32_t aOff = (uint32_t)((wm * 32 + (lane & 15)) * SHB + ((lane >> 4) & 1) * 16);
    uint32_t bRow = (uint32_t)(wn * 32 + (lane & 7) + ((lane >> 4) & 1) * 8);
    uint32_t gOff = 128 * SHB + bRow * SHB + ((lane >> 3) & 1) * 16;
    uint32_t uOff = 192 * SHB + bRow * SHB + ((lane >> 3) & 1) * 16;

    // prologue: issue tiles 0 and 1
    #pragma unroll
    for (int it = 0; it < 4; it++) cp16(dA[it], arow[it]);
    #pragma unroll
    for (int it = 0; it < 2; it++) { cp16(dG[it], grow[it]); cp16(dU[it], urow[it]); }
    cp_commit();
    #pragma unroll
    for (int it = 0; it < 4; it++) cp16(dA[it] + G1_BUF, arow[it] + KT);
    #pragma unroll
    for (int it = 0; it < 2; it++) { cp16(dG[it] + G1_BUF, grow[it] + KT); cp16(dU[it] + G1_BUF, urow[it] + KT); }
    cp_commit();

    uint32_t cur = 0, nxt = 2 * G1_BUF;
    for (int kt = 0; kt < NKT; kt++) {
        if (kt == NKT - 1) cp_wait<0>(); else cp_wait<1>();
        __syncthreads();

        uint32_t aB = sbase + cur + aOff;
        uint32_t gB = sbase + cur + gOff;
        uint32_t uB = sbase + cur + uOff;
        #pragma unroll
        for (int ks = 0; ks < 4; ks++) {
            uint32_t a[2][4], bg[2][4], bu[2][4];
            ldsm4(a[0], aB + ks * 32);
            ldsm4(a[1], aB + 16 * SHB + ks * 32);
            ldsm4(bg[0], gB + ks * 32);
            ldsm4(bg[1], gB + 16 * SHB + ks * 32);
            ldsm4(bu[0], uB + ks * 32);
            ldsm4(bu[1], uB + 16 * SHB + ks * 32);
            #pragma unroll
            for (int mt = 0; mt < 2; mt++)
                #pragma unroll
                for (int nt = 0; nt < 4; nt++) {
                    int g = nt >> 1, h = (nt & 1) * 2;
                    mma16(accg[mt][nt], a[mt], bg[g][h], bg[g][h + 1]);
                    mma16(accu[mt][nt], a[mt], bu[g][h], bu[g][h + 1]);
                }
        }
        __syncthreads();

        if (kt + 2 < NKT) {
            int ko = (kt + 2) * KT;
            #pragma unroll
            for (int it = 0; it < 4; it++) cp16(dA[it] + nxt, arow[it] + ko);
            #pragma unroll
            for (int it = 0; it < 2; it++) { cp16(dG[it] + nxt, grow[it] + ko); cp16(dU[it] + nxt, urow[it] + ko); }
            cp_commit();
        }
        cur = nxt;
        nxt += G1_BUF;
        if (nxt == 3 * G1_BUF) nxt = 0;
        // rotate: cur follows (kt+1)%3 pattern
        cur = (cur == 0) ? 0 : cur;  // no-op; cur was set to old nxt
        // fix ordering: cur should be (kt+1)%3*BUF. old nxt was (kt+2)%3*BUF. adjust:
        // we set cur=old nxt which is wrong by one stage; recompute properly below.
        if (kt + 1 < NKT) {
            cur = (uint32_t)(((kt + 1) % 3) * G1_BUF);
            nxt = (uint32_t)(((kt + 3) % 3) * G1_BUF);
        }
    }

    int base = g_offset[e];
    #pragma unroll
    for (int mt = 0; mt < 2; mt++) {
        #pragma unroll
        for (int half = 0; half < 2; half++) {
            int gm = m0 + wm * 32 + mt * 16 + (lane >> 2) + half * 8;
            if (gm < cnt) {
                __half* hp = &g_h[(size_t)(base + gm) * HIDDEN + n0 + wn * 32 + (lane & 3) * 2];
                #pragma unroll
                for (int nt = 0; nt < 4; nt++) {
                    float gx = accg[mt][nt][half * 2 + 0], ux = accu[mt][nt][half * 2 + 0];
                    float gy = accg[mt][nt][half * 2 + 1], uy = accu[mt][nt][half * 2 + 1];
                    *(__half2*)(hp + nt * 8) = __floats2half2_rn(silu(gx) * ux, silu(gy) * uy);
                }
            }
        }
    }
}

// ---------------- GEMM2 (fp16 mma): y = (h Wd^T) * wt ----------------
// Block 128(M) x 128(N), 256 thr, 3-stage cp.async pipeline.
#define G2_BUF  (256 * SHB)
#define G2_SMEM (3 * G2_BUF)
__global__ __launch_bounds__(256, 2) void k_gemm2() {
    extern __shared__ char smem[];
    int e   = blockIdx.z;
    int cnt = g_count[e];
    int m0  = blockIdx.y * 128;
    if (m0 >= cnt) return;
    int n0  = blockIdx.x * 128;
    int tid = threadIdx.x, lane = tid & 31, wid = tid >> 5;
    int wm  = wid & 1, wn = wid >> 1;

    const __half* Wd = g_wd16 + (size_t)e * DIM * HIDDEN;
    int base = g_offset[e];

    const __half* arow[4];
    const __half* brow[4];
    #pragma unroll
    for (int it = 0; it < 4; it++) {
        int flat = tid + it * 256;
        int m    = flat >> 3;
        int gm   = m0 + m;
        arow[it] = g_h + (size_t)(base + (gm < cnt ? gm : 0)) * HIDDEN + (flat & 7) * 8;
        brow[it] = Wd + (size_t)(n0 + m) * HIDDEN + (flat & 7) * 8;
    }
    uint32_t sbase = sptr(smem);
    uint32_t dA[4], dB[4];
    #pragma unroll
    for (int it = 0; it < 4; it++) {
        int flat = tid + it * 256;
        dA[it] = sbase + (uint32_t)((flat >> 3) * SHB + (flat & 7) * 16);
        dB[it] = dA[it] + 128 * SHB;
    }

    float acc[4][4][4];
    #pragma unroll
    for (int mt = 0; mt < 4; mt++)
        #pragma unroll
        for (int nt = 0; nt < 4; nt++)
            #pragma unroll
            for (int i = 0; i < 4; i++) acc[mt][nt][i] = 0.f;

    uint32_t aOff = (uint32_t)((wm * 64 + (lane & 15)) * SHB + ((lane >> 4) & 1) * 16);
    uint32_t bOff = 128 * SHB +
                    (uint32_t)((wn * 32 + (lane & 7) + ((lane >> 4) & 1) * 8) * SHB +
                               ((lane >> 3) & 1) * 16);

    #pragma unroll
    for (int it = 0; it < 4; it++) { cp16(dA[it], arow[it]); cp16(dB[it], brow[it]); }
    cp_commit();
    #pragma unroll
    for (int it = 0; it < 4; it++) { cp16(dA[it] + G2_BUF, arow[it] + KT); cp16(dB[it] + G2_BUF, brow[it] + KT); }
    cp_commit();

    for (int kt = 0; kt < NKT; kt++) {
        uint32_t cur = (uint32_t)((kt % 3) * G2_BUF);
        if (kt == NKT - 1) cp_wait<0>(); else cp_wait<1>();
        __syncthreads();

        uint32_t aB = sbase + cur + aOff;
        uint32_t bB = sbase + cur + bOff;
        #pragma unroll
        for (int ks = 0; ks < 4; ks++) {
            uint32_t a[4][4], b[2][4];
            #pragma unroll
            for (int mt = 0; mt < 4; mt++)
                ldsm4(a[mt], aB + mt * 16 * SHB + ks * 32);
            ldsm4(b[0], bB + ks * 32);
            ldsm4(b[1], bB + 16 * SHB + ks * 32);
            #pragma unroll
            for (int mt = 0; mt < 4; mt++)
                #pragma unroll
                for (int nt = 0; nt < 4; nt++) {
                    int g = nt >> 1, h = (nt & 1) * 2;
                    mma16(acc[mt][nt], a[mt], b[g][h], b[g][h + 1]);
                }
        }
        __syncthreads();

        if (kt + 2 < NKT) {
            uint32_t nxt = (uint32_t)(((kt + 2) % 3) * G2_BUF);
            int ko = (kt + 2) * KT;
            #pragma unroll
            for (int it = 0; it < 4; it++) { cp16(dA[it] + nxt, arow[it] + ko); cp16(dB[it] + nxt, brow[it] + ko); }
            cp_commit();
        }
    }

    #pragma unroll
    for (int mt = 0; mt < 4; mt++) {
        #pragma unroll
        for (int half = 0; half < 2; half++) {
            int gm = m0 + wm * 64 + mt * 16 + (lane >> 2) + half * 8;
            if (gm < cnt) {
                float w = g_wt[e * T_TOK + gm];
                float* yp = &g_y[(size_t)(base + gm) * DIM + n0 + wn * 32 + (lane & 3) * 2];
                #pragma unroll
                for (int nt = 0; nt < 4; nt++) {
                    float2 o;
                    o.x = acc[mt][nt][half * 2 + 0] * w;
                    o.y = acc[mt][nt][half * 2 + 1] * w;
                    *(float2*)(yp + nt * 8) = o;
                }
            }
        }
    }
}

// ---------------- combine ----------------
__global__ __launch_bounds__(256) void k_combine(float* __restrict__ out) {
    int t = blockIdx.x;
    int c = threadIdx.x * 4;
    int sA = g_offset[g_eA[t]] + g_pA[t];
    int sB = g_offset[g_eB[t]] + g_pB[t];
    float4 a = *(const float4*)&g_y[(size_t)sA * DIM + c];
    float4 b = *(const float4*)&g_y[(size_t)sB * DIM + c];
    *(float4*)&out[(size_t)t * DIM + c] = make_float4(a.x + b.x, a.y + b.y, a.z + b.z, a.w + b.w);
}

// ---------------- launch ----------------
extern "C" void kernel_launch(void* const* d_in, const int* in_sizes, int n_in,
                              void* d_out, int out_size) {
    const float* x         = (const float*)d_in[0];
    const float* gate_w    = (const float*)d_in[1];
    const float* gate_proj = (const float*)d_in[2];
    const float* up_proj   = (const float*)d_in[3];
    const float* down_proj = (const float*)d_in[4];
    float* out = (float*)d_out;

    cudaFuncSetAttribute(k_gemm1, cudaFuncAttributeMaxDynamicSharedMemorySize, G1_SMEM);
    cudaFuncSetAttribute(k_gemm2, cudaFuncAttributeMaxDynamicSharedMemorySize, G2_SMEM);

    int n4x = T_TOK * DIM / 4;
    int n4w = NE * HIDDEN * DIM / 4;
    // launch order chosen so k_gemm1 is launch #6 (ncu -s 5 -c 1 profiles it)
    k_zero_counts<<<1, 32>>>();
    k_router<<<T_TOK / 8, 256>>>(x, gate_w);
    k_offsets<<<1, 32>>>();
    k_convx<<<(n4x + 255) / 256, 256>>>(x, n4x);
    k_convw<<<dim3((n4w + 255) / 256, 3), 256>>>(gate_proj, up_proj, down_proj, n4w);
    k_gemm1<<<dim3(HIDDEN / 64, T_TOK / 128, NE), 256, G1_SMEM>>>();
    k_gemm2<<<dim3(DIM / 128, T_TOK / 128, NE), 256, G2_SMEM>>>();
    k_combine<<<T_TOK, 256>>>(out);
}

// round 8
// speedup vs baseline: 1.1445x; 1.0228x over previous
#include <cuda_runtime.h>
#include <cuda_fp16.h>
#include <math.h>
#include <stdint.h>

#define DIM     1024
#define HIDDEN  1024
#define NE      8
#define T_TOK   32768
#define KT      64          // k-tile in halfs (128B of fp16)
#define NKT     16          // 1024 / 64
#define SHB     144         // padded smem row bytes (72 halfs)

// ---------------- device scratch ----------------
__device__ int    g_count[NE];
__device__ int    g_offset[NE];
__device__ int    g_tok[NE * T_TOK];
__device__ float  g_wt[NE * T_TOK];
__device__ __align__(16) __half g_x16[(size_t)T_TOK * DIM];
__device__ __align__(16) __half g_wg16[(size_t)NE * HIDDEN * DIM];
__device__ __align__(16) __half g_wu16[(size_t)NE * HIDDEN * DIM];
__device__ __align__(16) __half g_wd16[(size_t)NE * DIM * HIDDEN];
__device__ __align__(16) __half g_h[(size_t)2 * T_TOK * HIDDEN];

// ---------------- helpers ----------------
__device__ __forceinline__ uint32_t sptr(const void* p) {
    return (uint32_t)__cvta_generic_to_shared(p);
}
__device__ __forceinline__ void cp16(uint32_t dst, const void* src) {
    asm volatile("cp.async.cg.shared.global [%0], [%1], 16;" :: "r"(dst), "l"(src));
}
__device__ __forceinline__ void cp_commit() {
    asm volatile("cp.async.commit_group;" ::: "memory");
}
template<int N> __device__ __forceinline__ void cp_wait() {
    asm volatile("cp.async.wait_group %0;" :: "n"(N) : "memory");
}
__device__ __forceinline__ void ldsm4(uint32_t* r, uint32_t a) {
    asm volatile("ldmatrix.sync.aligned.m8n8.x4.shared.b16 {%0,%1,%2,%3}, [%4];"
                 : "=r"(r[0]), "=r"(r[1]), "=r"(r[2]), "=r"(r[3]) : "r"(a));
}
__device__ __forceinline__ void mma16(float* c, const uint32_t* a, uint32_t b0, uint32_t b1) {
    asm volatile("mma.sync.aligned.m16n8k16.row.col.f32.f16.f16.f32 "
                 "{%0,%1,%2,%3},{%4,%5,%6,%7},{%8,%9},{%0,%1,%2,%3};"
                 : "+f"(c[0]), "+f"(c[1]), "+f"(c[2]), "+f"(c[3])
                 : "r"(a[0]), "r"(a[1]), "r"(a[2]), "r"(a[3]), "r"(b0), "r"(b1));
}
__device__ __forceinline__ float silu(float g) {
    return g * (1.f / (1.f + __expf(-g)));
}

// ---------------- fp32 -> fp16 conversions ----------------
__global__ __launch_bounds__(256) void k_convx(const float* __restrict__ s, int n4) {
    int i = blockIdx.x * 256 + threadIdx.x;
    if (i < n4) {
        float4 v = ((const float4*)s)[i];
        __half2* o = (__half2*)g_x16 + (size_t)i * 2;
        o[0] = __floats2half2_rn(v.x, v.y);
        o[1] = __floats2half2_rn(v.z, v.w);
    }
}
__global__ __launch_bounds__(256) void k_convw(const float* __restrict__ wg,
                                               const float* __restrict__ wu,
                                               const float* __restrict__ wd, int n4) {
    int which = blockIdx.y;
    const float* s = (which == 0) ? wg : (which == 1) ? wu : wd;
    __half* d = (which == 0) ? g_wg16 : (which == 1) ? g_wu16 : g_wd16;
    int i = blockIdx.x * 256 + threadIdx.x;
    if (i < n4) {
        float4 v = ((const float4*)s)[i];
        __half2* o = (__half2*)d + (size_t)i * 2;
        o[0] = __floats2half2_rn(v.x, v.y);
        o[1] = __floats2half2_rn(v.z, v.w);
    }
}

// ---------------- init / router ----------------
__global__ void k_zero_counts() { if (threadIdx.x < NE) g_count[threadIdx.x] = 0; }
__global__ void k_offsets() {
    if (threadIdx.x == 0) {
        int s = 0;
        #pragma unroll
        for (int e = 0; e < NE; e++) { g_offset[e] = s; s += g_count[e]; }
    }
}

__global__ __launch_bounds__(256) void k_router(const float* __restrict__ x,
                                                const float* __restrict__ gate_w) {
    int warp = blockIdx.x * 8 + (threadIdx.x >> 5);
    int lane = threadIdx.x & 31;
    if (warp >= T_TOK) return;
    const float* xr = x + (size_t)warp * DIM;
    float acc[NE];
    #pragma unroll
    for (int e = 0; e < NE; e++) acc[e] = 0.f;
    #pragma unroll
    for (int j = 0; j < DIM / 128; j++) {
        int d = j * 128 + lane * 4;
        float4 xv = *(const float4*)(xr + d);
        #pragma unroll
        for (int e = 0; e < NE; e++) {
            float4 gv = *(const float4*)(gate_w + e * DIM + d);
            acc[e] += xv.x * gv.x + xv.y * gv.y + xv.z * gv.z + xv.w * gv.w;
        }
    }
    #pragma unroll
    for (int off = 16; off > 0; off >>= 1)
        #pragma unroll
        for (int e = 0; e < NE; e++)
            acc[e] += __shfl_xor_sync(0xffffffffu, acc[e], off);
    if (lane == 0) {
        int i0 = 0;
        #pragma unroll
        for (int e = 1; e < NE; e++) if (acc[e] > acc[i0]) i0 = e;
        int i1 = -1;
        #pragma unroll
        for (int e = 0; e < NE; e++) {
            if (e == i0) continue;
            if (i1 < 0 || acc[e] > acc[i1]) i1 = e;
        }
        float s0 = 1.f / (1.f + expf(-acc[i0]));
        float s1 = 1.f / (1.f + expf(-acc[i1]));
        float inv = 1.f / (s0 + s1 + 1e-9f);
        int p0 = atomicAdd(&g_count[i0], 1);
        g_tok[i0 * T_TOK + p0] = warp; g_wt[i0 * T_TOK + p0] = s0 * inv;
        int p1 = atomicAdd(&g_count[i1], 1);
        g_tok[i1 * T_TOK + p1] = warp; g_wt[i1 * T_TOK + p1] = s1 * inv;
    }
}

// ---------------- GEMM1 (fp16 mma): h = silu(Xg Wg^T) * (Xg Wu^T) ----------------
// Block 128(M) x 64(N) dual-B, 256 thr, 3-stage cp.async pipeline, one barrier/iter.
#define G1_BUF  (256 * SHB)
#define G1_SMEM (3 * G1_BUF)
__global__ __launch_bounds__(256, 2) void k_gemm1() {
    extern __shared__ char smem[];
    int e   = blockIdx.z;
    int cnt = g_count[e];
    int m0  = blockIdx.y * 128;
    if (m0 >= cnt) return;
    int n0  = blockIdx.x * 64;
    int tid = threadIdx.x, lane = tid & 31, wid = tid >> 5;
    int wm  = wid & 3, wn = wid >> 2;

    const __half* Wg = g_wg16 + (size_t)e * HIDDEN * DIM;
    const __half* Wu = g_wu16 + (size_t)e * HIDDEN * DIM;

    const __half* arow[4];
    #pragma unroll
    for (int it = 0; it < 4; it++) {
        int flat = tid + it * 256;
        int m    = flat >> 3;
        int gm   = m0 + m;
        int tok  = g_tok[e * T_TOK + (gm < cnt ? gm : 0)];
        arow[it] = g_x16 + (size_t)tok * DIM + (flat & 7) * 8;
    }
    const __half* grow[2];
    const __half* urow[2];
    #pragma unroll
    for (int it = 0; it < 2; it++) {
        int flat = tid + it * 256;
        int n    = flat >> 3;
        grow[it] = Wg + (size_t)(n0 + n) * DIM + (flat & 7) * 8;
        urow[it] = Wu + (size_t)(n0 + n) * DIM + (flat & 7) * 8;
    }
    uint32_t sbase = sptr(smem);
    uint32_t dA[4], dG[2], dU[2];
    #pragma unroll
    for (int it = 0; it < 4; it++) {
        int flat = tid + it * 256;
        dA[it] = sbase + (uint32_t)((flat >> 3) * SHB + (flat & 7) * 16);
    }
    #pragma unroll
    for (int it = 0; it < 2; it++) {
        int flat = tid + it * 256;
        dG[it] = sbase + (uint32_t)(128 * SHB + (flat >> 3) * SHB + (flat & 7) * 16);
        dU[it] = sbase + (uint32_t)(192 * SHB + (flat >> 3) * SHB + (flat & 7) * 16);
    }

    float accg[2][4][4], accu[2][4][4];
    #pragma unroll
    for (int mt = 0; mt < 2; mt++)
        #pragma unroll
        for (int nt = 0; nt < 4; nt++)
            #pragma unroll
            for (int i = 0; i < 4; i++) { accg[mt][nt][i] = 0.f; accu[mt][nt][i] = 0.f; }

    uint32_t aOff = (uint32_t)((wm * 32 + (lane & 15)) * SHB + ((lane >> 4) & 1) * 16);
    uint32_t bRow = (uint32_t)(wn * 32 + (lane & 7) + ((lane >> 4) & 1) * 8);
    uint32_t gOff = 128 * SHB + bRow * SHB + ((lane >> 3) & 1) * 16;
    uint32_t uOff = 192 * SHB + bRow * SHB + ((lane >> 3) & 1) * 16;

    // prologue: tiles 0 and 1 into buffers 0 and 1
    #pragma unroll
    for (int it = 0; it < 4; it++) cp16(dA[it], arow[it]);
    #pragma unroll
    for (int it = 0; it < 2; it++) { cp16(dG[it], grow[it]); cp16(dU[it], urow[it]); }
    cp_commit();
    #pragma unroll
    for (int it = 0; it < 4; it++) cp16(dA[it] + G1_BUF, arow[it] + KT);
    #pragma unroll
    for (int it = 0; it < 2; it++) { cp16(dG[it] + G1_BUF, grow[it] + KT); cp16(dU[it] + G1_BUF, urow[it] + KT); }
    cp_commit();

    for (int kt = 0; kt < NKT; kt++) {
        uint32_t cur = (uint32_t)((kt % 3) * G1_BUF);
        if (kt == NKT - 1) cp_wait<0>(); else cp_wait<1>();
        __syncthreads();   // single barrier per iteration: all tiles-kt data visible to all warps

        if (kt + 2 < NKT) {        // prefetch into (kt+2)%3 — disjoint from kt%3 and (kt+1)%3
            uint32_t nxt = (uint32_t)(((kt + 2) % 3) * G1_BUF);
            int ko = (kt + 2) * KT;
            #pragma unroll
            for (int it = 0; it < 4; it++) cp16(dA[it] + nxt, arow[it] + ko);
            #pragma unroll
            for (int it = 0; it < 2; it++) { cp16(dG[it] + nxt, grow[it] + ko); cp16(dU[it] + nxt, urow[it] + ko); }
            cp_commit();
        }

        uint32_t aB = sbase + cur + aOff;
        uint32_t gB = sbase + cur + gOff;
        uint32_t uB = sbase + cur + uOff;
        #pragma unroll
        for (int ks = 0; ks < 4; ks++) {
            uint32_t a[2][4], bg[2][4], bu[2][4];
            ldsm4(a[0], aB + ks * 32);
            ldsm4(a[1], aB + 16 * SHB + ks * 32);
            ldsm4(bg[0], gB + ks * 32);
            ldsm4(bg[1], gB + 16 * SHB + ks * 32);
            ldsm4(bu[0], uB + ks * 32);
            ldsm4(bu[1], uB + 16 * SHB + ks * 32);
            #pragma unroll
            for (int mt = 0; mt < 2; mt++)
                #pragma unroll
                for (int nt = 0; nt < 4; nt++) {
                    int g = nt >> 1, h = (nt & 1) * 2;
                    mma16(accg[mt][nt], a[mt], bg[g][h], bg[g][h + 1]);
                    mma16(accu[mt][nt], a[mt], bu[g][h], bu[g][h + 1]);
                }
        }
    }

    int base = g_offset[e];
    #pragma unroll
    for (int mt = 0; mt < 2; mt++) {
        #pragma unroll
        for (int half = 0; half < 2; half++) {
            int gm = m0 + wm * 32 + mt * 16 + (lane >> 2) + half * 8;
            if (gm < cnt) {
                __half* hp = &g_h[(size_t)(base + gm) * HIDDEN + n0 + wn * 32 + (lane & 3) * 2];
                #pragma unroll
                for (int nt = 0; nt < 4; nt++) {
                    float gx = accg[mt][nt][half * 2 + 0], ux = accu[mt][nt][half * 2 + 0];
                    float gy = accg[mt][nt][half * 2 + 1], uy = accu[mt][nt][half * 2 + 1];
                    *(__half2*)(hp + nt * 8) = __floats2half2_rn(silu(gx) * ux, silu(gy) * uy);
                }
            }
        }
    }
}

// ---------------- GEMM2 (fp16 mma): out += (h Wd^T) * wt  (atomic, 2 adds/elem) ----------------
#define G2_BUF  (256 * SHB)
#define G2_SMEM (3 * G2_BUF)
__global__ __launch_bounds__(256, 2) void k_gemm2(float* __restrict__ out) {
    extern __shared__ char smem[];
    int e   = blockIdx.z;
    int cnt = g_count[e];
    int m0  = blockIdx.y * 128;
    if (m0 >= cnt) return;
    int n0  = blockIdx.x * 128;
    int tid = threadIdx.x, lane = tid & 31, wid = tid >> 5;
    int wm  = wid & 1, wn = wid >> 1;

    const __half* Wd = g_wd16 + (size_t)e * DIM * HIDDEN;
    int base = g_offset[e];

    const __half* arow[4];
    const __half* brow[4];
    #pragma unroll
    for (int it = 0; it < 4; it++) {
        int flat = tid + it * 256;
        int m    = flat >> 3;
        int gm   = m0 + m;
        arow[it] = g_h + (size_t)(base + (gm < cnt ? gm : 0)) * HIDDEN + (flat & 7) * 8;
        brow[it] = Wd + (size_t)(n0 + m) * HIDDEN + (flat & 7) * 8;
    }
    uint32_t sbase = sptr(smem);
    uint32_t dA[4], dB[4];
    #pragma unroll
    for (int it = 0; it < 4; it++) {
        int flat = tid + it * 256;
        dA[it] = sbase + (uint32_t)((flat >> 3) * SHB + (flat & 7) * 16);
        dB[it] = dA[it] + 128 * SHB;
    }

    float acc[4][4][4];
    #pragma unroll
    for (int mt = 0; mt < 4; mt++)
        #pragma unroll
        for (int nt = 0; nt < 4; nt++)
            #pragma unroll
            for (int i = 0; i < 4; i++) acc[mt][nt][i] = 0.f;

    uint32_t aOff = (uint32_t)((wm * 64 + (lane & 15)) * SHB + ((lane >> 4) & 1) * 16);
    uint32_t bOff = 128 * SHB +
                    (uint32_t)((wn * 32 + (lane & 7) + ((lane >> 4) & 1) * 8) * SHB +
                               ((lane >> 3) & 1) * 16);

    #pragma unroll
    for (int it = 0; it < 4; it++) { cp16(dA[it], arow[it]); cp16(dB[it], brow[it]); }
    cp_commit();
    #pragma unroll
    for (int it = 0; it < 4; it++) { cp16(dA[it] + G2_BUF, arow[it] + KT); cp16(dB[it] + G2_BUF, brow[it] + KT); }
    cp_commit();

    for (int kt = 0; kt < NKT; kt++) {
        uint32_t cur = (uint32_t)((kt % 3) * G2_BUF);
        if (kt == NKT - 1) cp_wait<0>(); else cp_wait<1>();
        __syncthreads();

        if (kt + 2 < NKT) {
            uint32_t nxt = (uint32_t)(((kt + 2) % 3) * G2_BUF);
            int ko = (kt + 2) * KT;
            #pragma unroll
            for (int it = 0; it < 4; it++) { cp16(dA[it] + nxt, arow[it] + ko); cp16(dB[it] + nxt, brow[it] + ko); }
            cp_commit();
        }

        uint32_t aB = sbase + cur + aOff;
        uint32_t bB = sbase + cur + bOff;
        #pragma unroll
        for (int ks = 0; ks < 4; ks++) {
            uint32_t a[4][4], b[2][4];
            #pragma unroll
            for (int mt = 0; mt < 4; mt++)
                ldsm4(a[mt], aB + mt * 16 * SHB + ks * 32);
            ldsm4(b[0], bB + ks * 32);
            ldsm4(b[1], bB + 16 * SHB + ks * 32);
            #pragma unroll
            for (int mt = 0; mt < 4; mt++)
                #pragma unroll
                for (int nt = 0; nt < 4; nt++) {
                    int g = nt >> 1, h = (nt & 1) * 2;
                    mma16(acc[mt][nt], a[mt], b[g][h], b[g][h + 1]);
                }
        }
    }

    #pragma unroll
    for (int mt = 0; mt < 4; mt++) {
        #pragma unroll
        for (int half = 0; half < 2; half++) {
            int gm = m0 + wm * 64 + mt * 16 + (lane >> 2) + half * 8;
            if (gm < cnt) {
                float w   = g_wt[e * T_TOK + gm];
                int   tok = g_tok[e * T_TOK + gm];
                float* op = out + (size_t)tok * DIM + n0 + wn * 32 + (lane & 3) * 2;
                #pragma unroll
                for (int nt = 0; nt < 4; nt++) {
                    atomicAdd(op + nt * 8 + 0, acc[mt][nt][half * 2 + 0] * w);
                    atomicAdd(op + nt * 8 + 1, acc[mt][nt][half * 2 + 1] * w);
                }
            }
        }
    }
}

// ---------------- launch ----------------
extern "C" void kernel_launch(void* const* d_in, const int* in_sizes, int n_in,
                              void* d_out, int out_size) {
    const float* x         = (const float*)d_in[0];
    const float* gate_w    = (const float*)d_in[1];
    const float* gate_proj = (const float*)d_in[2];
    const float* up_proj   = (const float*)d_in[3];
    const float* down_proj = (const float*)d_in[4];
    float* out = (float*)d_out;

    cudaFuncSetAttribute(k_gemm1, cudaFuncAttributeMaxDynamicSharedMemorySize, G1_SMEM);
    cudaFuncSetAttribute(k_gemm2, cudaFuncAttributeMaxDynamicSharedMemorySize, G2_SMEM);

    int n4x = T_TOK * DIM / 4;
    int n4w = NE * HIDDEN * DIM / 4;

    cudaMemsetAsync(out, 0, (size_t)out_size * sizeof(float), 0);
    k_zero_counts<<<1, 32>>>();
    k_router<<<T_TOK / 8, 256>>>(x, gate_w);
    k_offsets<<<1, 32>>>();
    k_convx<<<(n4x + 255) / 256, 256>>>(x, n4x);
    k_convw<<<dim3((n4w + 255) / 256, 3), 256>>>(gate_proj, up_proj, down_proj, n4w);
    k_gemm1<<<dim3(HIDDEN / 64, T_TOK / 128, NE), 256, G1_SMEM>>>();
    k_gemm2<<<dim3(DIM / 128, T_TOK / 128, NE), 256, G2_SMEM>>>(out);
}